// round 16
// baseline (speedup 1.0000x reference)
#include <cuda_runtime.h>
#include <cstdint>

// FFN_36867999269234 via mma.sync m16n8k16.f16 (f32 accum).
// R15 = R14 (ncu-best 27.55us, regs 134) with __launch_bounds__(128,4):
// R14's register count is only 6 over the 128 boundary, so a gentle cap buys
// a 4th CTA/SM (12 -> 16 warps/SM, +33% latency-hiding) without the R10-style
// schedule starvation (that was a 38% reg cut; this is 4%).
// Structure unchanged: 2 tiles/warp, LN-ahead in the MMA shadow, bias as mma
// C-operand, relu as max.f16x2 post-pack, coalesced K/N-permuted ownership.

#define H 16
#define DM 64
#define LN_EPS 1e-5f

__device__ __forceinline__ uint32_t packh2(float lo, float hi) {
    uint32_t r;
    asm("cvt.rn.f16x2.f32 %0, %1, %2;" : "=r"(r) : "f"(hi), "f"(lo));
    return r;
}
__device__ __forceinline__ uint32_t relu2(uint32_t v) {
    uint32_t r;
    asm("max.f16x2 %0, %1, %2;" : "=r"(r) : "r"(v), "r"(0u));
    return r;
}

// d = a*b + {cx,cy,cx,cy}  (fresh D regs; C read directly from bias regs)
__device__ __forceinline__ void mma_f16_bias(float* d, const uint32_t* a,
                                             const uint32_t* b,
                                             float cx, float cy) {
    asm volatile(
        "mma.sync.aligned.m16n8k16.row.col.f32.f16.f16.f32 "
        "{%0,%1,%2,%3}, {%4,%5,%6,%7}, {%8,%9}, {%10,%11,%10,%11};"
        : "=f"(d[0]), "=f"(d[1]), "=f"(d[2]), "=f"(d[3])
        : "r"(a[0]), "r"(a[1]), "r"(a[2]), "r"(a[3]), "r"(b[0]), "r"(b[1]),
          "f"(cx), "f"(cy));
}
// c += a*b  (accumulate in place)
__device__ __forceinline__ void mma_f16(float* c, const uint32_t* a, const uint32_t* b) {
    asm volatile(
        "mma.sync.aligned.m16n8k16.row.col.f32.f16.f16.f32 "
        "{%0,%1,%2,%3}, {%4,%5,%6,%7}, {%8,%9}, {%0,%1,%2,%3};"
        : "+f"(c[0]), "+f"(c[1]), "+f"(c[2]), "+f"(c[3])
        : "r"(a[0]), "r"(a[1]), "r"(a[2]), "r"(a[3]), "r"(b[0]), "r"(b[1]));
}

// LN + A1 fragment (xa = row g cols 4q..4q+3, xb = row g+8); K-permuted slots.
__device__ __forceinline__ void ln_to_frag(const float4 xa, const float4 xb,
                                           uint32_t* A) {
    float s0 = (xa.x + xa.y) + (xa.z + xa.w);
    float s1 = (xb.x + xb.y) + (xb.z + xb.w);
    float q0 = fmaf(xa.x, xa.x, xa.y * xa.y) + fmaf(xa.z, xa.z, xa.w * xa.w);
    float q1 = fmaf(xb.x, xb.x, xb.y * xb.y) + fmaf(xb.z, xb.z, xb.w * xb.w);
    s0 += __shfl_xor_sync(0xFFFFFFFFu, s0, 1);
    s1 += __shfl_xor_sync(0xFFFFFFFFu, s1, 1);
    q0 += __shfl_xor_sync(0xFFFFFFFFu, q0, 1);
    q1 += __shfl_xor_sync(0xFFFFFFFFu, q1, 1);
    s0 += __shfl_xor_sync(0xFFFFFFFFu, s0, 2);
    s1 += __shfl_xor_sync(0xFFFFFFFFu, s1, 2);
    q0 += __shfl_xor_sync(0xFFFFFFFFu, q0, 2);
    q1 += __shfl_xor_sync(0xFFFFFFFFu, q1, 2);
    const float m0 = s0 * (1.f / H);
    const float m1 = s1 * (1.f / H);
    const float r0 = rsqrtf(q0 * (1.f / H) - m0 * m0 + LN_EPS);
    const float r1 = rsqrtf(q1 * (1.f / H) - m1 * m1 + LN_EPS);
    A[0] = packh2((xa.x - m0) * r0, (xa.y - m0) * r0);
    A[1] = packh2((xb.x - m1) * r1, (xb.y - m1) * r1);
    A[2] = packh2((xa.z - m0) * r0, (xa.w - m0) * r0);
    A[3] = packh2((xb.z - m1) * r1, (xb.w - m1) * r1);
}

__global__ __launch_bounds__(128, 4) void ffn_mma(
    const float* __restrict__ x,
    const float* __restrict__ gamma,
    const float* __restrict__ beta,
    const float* __restrict__ w1,   // [DM, H]
    const float* __restrict__ b1,   // [DM]
    const float* __restrict__ w2,   // [H, DM]
    const float* __restrict__ b2,   // [H]
    float* __restrict__ out,
    int ntok)
{
    __shared__ float2 c1bs[8][4];   // folded b1, [h-ntile j][q]
    __shared__ float2 c2bs[2][4];   // b2 (physical perm), [jn][q]

    const int tid  = threadIdx.x;
    const int wid  = tid >> 5;
    const int lane = tid & 31;
    const int g = lane >> 2;
    const int q = lane & 3;

    // ---- B1 fragments (K-permuted to match coalesced x ownership) ----
    uint32_t B1[8][2];
    #pragma unroll
    for (int j = 0; j < 8; j++) {
        const float* wr = w1 + (8 * j + g) * H;
        B1[j][0] = packh2(wr[4 * q]     * gamma[4 * q],     wr[4 * q + 1] * gamma[4 * q + 1]);
        B1[j][1] = packh2(wr[4 * q + 2] * gamma[4 * q + 2], wr[4 * q + 3] * gamma[4 * q + 3]);
    }
    // ---- B2 fragments (N-permuted: logical n=8jn+g -> physical row rn) ----
    uint32_t B2[4][2][2];
    #pragma unroll
    for (int s = 0; s < 4; s++)
        #pragma unroll
        for (int jn = 0; jn < 2; jn++) {
            const int rn = 4 * (g >> 1) + 2 * jn + (g & 1);
            const float* wr = w2 + rn * DM + 16 * s;
            B2[s][jn][0] = packh2(wr[2 * q],     wr[2 * q + 1]);
            B2[s][jn][1] = packh2(wr[2 * q + 8], wr[2 * q + 9]);
        }

    // ---- bias LUTs (smem; compiler hoists the per-lane loads) ----
    if (tid < 32) {
        int j = tid >> 2, qq = tid & 3;
        float a0 = b1[8 * j + 2 * qq], a1 = b1[8 * j + 2 * qq + 1];
        #pragma unroll
        for (int k = 0; k < H; k++) {
            a0 = fmaf(w1[(8 * j + 2 * qq) * H + k],     beta[k], a0);
            a1 = fmaf(w1[(8 * j + 2 * qq + 1) * H + k], beta[k], a1);
        }
        c1bs[j][qq] = make_float2(a0, a1);
    }
    if (tid < 8) {
        int jn = (tid >> 2) & 1, qq = tid & 3;
        c2bs[jn][qq] = make_float2(b2[4 * qq + 2 * jn], b2[4 * qq + 2 * jn + 1]);
    }
    __syncthreads();

    // ---------- token loop: 32 tokens (2 tiles) per warp-iteration ----------
    const int npairs = ntok >> 5;             // ntok multiple of 32
    const int wstep  = gridDim.x * 4;
    const int wp0    = blockIdx.x * 4 + wid;
    if (wp0 >= npairs) return;

    const long long e0 = (long long)g * H + 4 * q;          // row g
    const long long e1 = (long long)(g + 8) * H + 4 * q;    // row g+8

    auto loadpair = [&](int wp, float4& aA, float4& bA, float4& aB, float4& bB) {
        const float* p = x + ((long long)wp << 9);   // wp*32*H
        aA = *(const float4*)(p + e0);
        bA = *(const float4*)(p + e1);
        aB = *(const float4*)(p + 256 + e0);
        bB = *(const float4*)(p + 256 + e1);
    };

    // preamble: current pair loaded AND its A1 fragments ready
    float4 vaA, vbA, vaB, vbB;
    loadpair(wp0, vaA, vbA, vaB, vbB);
    uint32_t A1A[4], A1B[4];
    ln_to_frag(vaA, vbA, A1A);
    ln_to_frag(vaB, vbB, A1B);

    for (int wp = wp0; wp < npairs; wp += wstep) {
        // ---- prefetch next pair ----
        float4 naA, nbA, naB, nbB;
        {
            int nwp = wp + wstep;
            if (nwp >= npairs) nwp = wp;
            loadpair(nwp, naA, nbA, naB, nbB);
        }

        // ---- MMA1 tile A -> pack A2A (A1 ready from previous iteration) ----
        uint32_t A2A[4][4], A2B[4][4];
        {
            float C1[8][4];
            #pragma unroll
            for (int j = 0; j < 8; j++) {
                const float2 b = c1bs[j][q];
                mma_f16_bias(C1[j], A1A, B1[j], b.x, b.y);
            }
            #pragma unroll
            for (int s = 0; s < 4; s++) {
                A2A[s][0] = relu2(packh2(C1[2 * s][0],     C1[2 * s][1]));
                A2A[s][1] = relu2(packh2(C1[2 * s][2],     C1[2 * s][3]));
                A2A[s][2] = relu2(packh2(C1[2 * s + 1][0], C1[2 * s + 1][1]));
                A2A[s][3] = relu2(packh2(C1[2 * s + 1][2], C1[2 * s + 1][3]));
            }
        }
        // ---- MMA1 tile B -> pack A2B ----
        {
            float C1[8][4];
            #pragma unroll
            for (int j = 0; j < 8; j++) {
                const float2 b = c1bs[j][q];
                mma_f16_bias(C1[j], A1B, B1[j], b.x, b.y);
            }
            #pragma unroll
            for (int s = 0; s < 4; s++) {
                A2B[s][0] = relu2(packh2(C1[2 * s][0],     C1[2 * s][1]));
                A2B[s][1] = relu2(packh2(C1[2 * s][2],     C1[2 * s][3]));
                A2B[s][2] = relu2(packh2(C1[2 * s + 1][0], C1[2 * s + 1][1]));
                A2B[s][3] = relu2(packh2(C1[2 * s + 1][2], C1[2 * s + 1][3]));
            }
        }

        // ---- LN-AHEAD: A1 fragments for NEXT pair, in the MMA shadow ----
        uint32_t A1nA[4], A1nB[4];
        ln_to_frag(naA, nbA, A1nA);
        ln_to_frag(naB, nbB, A1nB);

        // ---- MMA2: four independent chains, bias-init on first k-step ----
        float C2A[2][4], C2B[2][4];
        {
            const float2 b0 = c2bs[0][q];
            const float2 b1v = c2bs[1][q];
            mma_f16_bias(C2A[0], A2A[0], B2[0][0], b0.x, b0.y);
            mma_f16_bias(C2B[0], A2B[0], B2[0][0], b0.x, b0.y);
            mma_f16_bias(C2A[1], A2A[0], B2[0][1], b1v.x, b1v.y);
            mma_f16_bias(C2B[1], A2B[0], B2[0][1], b1v.x, b1v.y);
        }
        #pragma unroll
        for (int s = 1; s < 4; s++) {
            mma_f16(C2A[0], A2A[s], B2[s][0]);
            mma_f16(C2B[0], A2B[s], B2[s][0]);
            mma_f16(C2A[1], A2A[s], B2[s][1]);
            mma_f16(C2B[1], A2B[s], B2[s][1]);
        }

        // ---- residual + coalesced STG.128 (both tiles) ----
        {
            float* p = out + ((long long)wp << 9);
            *(float4*)(p + e0)       = make_float4(C2A[0][0] + vaA.x, C2A[0][1] + vaA.y,
                                                   C2A[1][0] + vaA.z, C2A[1][1] + vaA.w);
            *(float4*)(p + e1)       = make_float4(C2A[0][2] + vbA.x, C2A[0][3] + vbA.y,
                                                   C2A[1][2] + vbA.z, C2A[1][3] + vbA.w);
            *(float4*)(p + 256 + e0) = make_float4(C2B[0][0] + vaB.x, C2B[0][1] + vaB.y,
                                                   C2B[1][0] + vaB.z, C2B[1][1] + vaB.w);
            *(float4*)(p + 256 + e1) = make_float4(C2B[0][2] + vbB.x, C2B[0][3] + vbB.y,
                                                   C2B[1][2] + vbB.z, C2B[1][3] + vbB.w);
        }

        // ---- rotate ----
        vaA = naA; vbA = nbA; vaB = naB; vbB = nbB;
        A1A[0] = A1nA[0]; A1A[1] = A1nA[1]; A1A[2] = A1nA[2]; A1A[3] = A1nA[3];
        A1B[0] = A1nB[0]; A1B[1] = A1nB[1]; A1B[2] = A1nB[2]; A1B[3] = A1nB[3];
    }
}

extern "C" void kernel_launch(void* const* d_in, const int* in_sizes, int n_in,
                              void* d_out, int out_size) {
    const float* x     = (const float*)d_in[0];
    const float* gamma = (const float*)d_in[1];
    const float* beta  = (const float*)d_in[2];
    const float* w1    = (const float*)d_in[3];
    const float* b1    = (const float*)d_in[4];
    const float* w2    = (const float*)d_in[5];
    const float* b2    = (const float*)d_in[6];
    float* out         = (float*)d_out;

    const int ntok = in_sizes[0] / H;   // 1,048,576 (multiple of 32)
    const int threads = 128;            // 4 warps x 32 tokens
    int blocks = 148 * 4;               // persistent grid-stride, 4 CTAs/SM
    ffn_mma<<<blocks, threads>>>(x, gamma, beta, w1, b1, w2, b2, out, ntok);
}

// round 17
// speedup vs baseline: 1.0877x; 1.0877x over previous
#include <cuda_runtime.h>
#include <cstdint>

// FFN_36867999269234 via mma.sync m16n8k16.f16 (f32 accum).
// R16 = R14 (ncu-best 27.55us) + proper 3-stage pipeline:
//   stage 0 (this iter):  MMA1/MMA2/store for pair i (A1 ready)
//   stage 1 (LN-ahead):   A1 fragments for pair i+1 (x loaded LAST iter)
//   stage 2 (prefetch):   LDG x for pair i+2
// R14 computed LN-ahead from loads issued the SAME iteration (~one MMA-phase
// of slack < DRAM latency). Distance-2 prefetch gives those loads a full
// iteration (~2000 cyc) to land, so LN-ahead never stalls on long_scoreboard.
// Everything else identical to R14: 2 tiles/warp, bias as mma C-operand,
// relu as max.f16x2 post-pack, coalesced K/N-permuted fragment ownership,
// launch_bounds(128,3), grid 148*3.

#define H 16
#define DM 64
#define LN_EPS 1e-5f

__device__ __forceinline__ uint32_t packh2(float lo, float hi) {
    uint32_t r;
    asm("cvt.rn.f16x2.f32 %0, %1, %2;" : "=r"(r) : "f"(hi), "f"(lo));
    return r;
}
__device__ __forceinline__ uint32_t relu2(uint32_t v) {
    uint32_t r;
    asm("max.f16x2 %0, %1, %2;" : "=r"(r) : "r"(v), "r"(0u));
    return r;
}

// d = a*b + {cx,cy,cx,cy}  (fresh D regs; C read directly from bias regs)
__device__ __forceinline__ void mma_f16_bias(float* d, const uint32_t* a,
                                             const uint32_t* b,
                                             float cx, float cy) {
    asm volatile(
        "mma.sync.aligned.m16n8k16.row.col.f32.f16.f16.f32 "
        "{%0,%1,%2,%3}, {%4,%5,%6,%7}, {%8,%9}, {%10,%11,%10,%11};"
        : "=f"(d[0]), "=f"(d[1]), "=f"(d[2]), "=f"(d[3])
        : "r"(a[0]), "r"(a[1]), "r"(a[2]), "r"(a[3]), "r"(b[0]), "r"(b[1]),
          "f"(cx), "f"(cy));
}
// c += a*b  (accumulate in place)
__device__ __forceinline__ void mma_f16(float* c, const uint32_t* a, const uint32_t* b) {
    asm volatile(
        "mma.sync.aligned.m16n8k16.row.col.f32.f16.f16.f32 "
        "{%0,%1,%2,%3}, {%4,%5,%6,%7}, {%8,%9}, {%0,%1,%2,%3};"
        : "+f"(c[0]), "+f"(c[1]), "+f"(c[2]), "+f"(c[3])
        : "r"(a[0]), "r"(a[1]), "r"(a[2]), "r"(a[3]), "r"(b[0]), "r"(b[1]));
}

// LN + A1 fragment (xa = row g cols 4q..4q+3, xb = row g+8); K-permuted slots.
__device__ __forceinline__ void ln_to_frag(const float4 xa, const float4 xb,
                                           uint32_t* A) {
    float s0 = (xa.x + xa.y) + (xa.z + xa.w);
    float s1 = (xb.x + xb.y) + (xb.z + xb.w);
    float q0 = fmaf(xa.x, xa.x, xa.y * xa.y) + fmaf(xa.z, xa.z, xa.w * xa.w);
    float q1 = fmaf(xb.x, xb.x, xb.y * xb.y) + fmaf(xb.z, xb.z, xb.w * xb.w);
    s0 += __shfl_xor_sync(0xFFFFFFFFu, s0, 1);
    s1 += __shfl_xor_sync(0xFFFFFFFFu, s1, 1);
    q0 += __shfl_xor_sync(0xFFFFFFFFu, q0, 1);
    q1 += __shfl_xor_sync(0xFFFFFFFFu, q1, 1);
    s0 += __shfl_xor_sync(0xFFFFFFFFu, s0, 2);
    s1 += __shfl_xor_sync(0xFFFFFFFFu, s1, 2);
    q0 += __shfl_xor_sync(0xFFFFFFFFu, q0, 2);
    q1 += __shfl_xor_sync(0xFFFFFFFFu, q1, 2);
    const float m0 = s0 * (1.f / H);
    const float m1 = s1 * (1.f / H);
    const float r0 = rsqrtf(q0 * (1.f / H) - m0 * m0 + LN_EPS);
    const float r1 = rsqrtf(q1 * (1.f / H) - m1 * m1 + LN_EPS);
    A[0] = packh2((xa.x - m0) * r0, (xa.y - m0) * r0);
    A[1] = packh2((xb.x - m1) * r1, (xb.y - m1) * r1);
    A[2] = packh2((xa.z - m0) * r0, (xa.w - m0) * r0);
    A[3] = packh2((xb.z - m1) * r1, (xb.w - m1) * r1);
}

__global__ __launch_bounds__(128, 3) void ffn_mma(
    const float* __restrict__ x,
    const float* __restrict__ gamma,
    const float* __restrict__ beta,
    const float* __restrict__ w1,   // [DM, H]
    const float* __restrict__ b1,   // [DM]
    const float* __restrict__ w2,   // [H, DM]
    const float* __restrict__ b2,   // [H]
    float* __restrict__ out,
    int ntok)
{
    __shared__ float2 c1bs[8][4];   // folded b1, [h-ntile j][q]
    __shared__ float2 c2bs[2][4];   // b2 (physical perm), [jn][q]

    const int tid  = threadIdx.x;
    const int wid  = tid >> 5;
    const int lane = tid & 31;
    const int g = lane >> 2;
    const int q = lane & 3;

    // ---- B1 fragments (K-permuted to match coalesced x ownership) ----
    uint32_t B1[8][2];
    #pragma unroll
    for (int j = 0; j < 8; j++) {
        const float* wr = w1 + (8 * j + g) * H;
        B1[j][0] = packh2(wr[4 * q]     * gamma[4 * q],     wr[4 * q + 1] * gamma[4 * q + 1]);
        B1[j][1] = packh2(wr[4 * q + 2] * gamma[4 * q + 2], wr[4 * q + 3] * gamma[4 * q + 3]);
    }
    // ---- B2 fragments (N-permuted: logical n=8jn+g -> physical row rn) ----
    uint32_t B2[4][2][2];
    #pragma unroll
    for (int s = 0; s < 4; s++)
        #pragma unroll
        for (int jn = 0; jn < 2; jn++) {
            const int rn = 4 * (g >> 1) + 2 * jn + (g & 1);
            const float* wr = w2 + rn * DM + 16 * s;
            B2[s][jn][0] = packh2(wr[2 * q],     wr[2 * q + 1]);
            B2[s][jn][1] = packh2(wr[2 * q + 8], wr[2 * q + 9]);
        }

    // ---- bias LUTs (smem; compiler hoists the per-lane loads) ----
    if (tid < 32) {
        int j = tid >> 2, qq = tid & 3;
        float a0 = b1[8 * j + 2 * qq], a1 = b1[8 * j + 2 * qq + 1];
        #pragma unroll
        for (int k = 0; k < H; k++) {
            a0 = fmaf(w1[(8 * j + 2 * qq) * H + k],     beta[k], a0);
            a1 = fmaf(w1[(8 * j + 2 * qq + 1) * H + k], beta[k], a1);
        }
        c1bs[j][qq] = make_float2(a0, a1);
    }
    if (tid < 8) {
        int jn = (tid >> 2) & 1, qq = tid & 3;
        c2bs[jn][qq] = make_float2(b2[4 * qq + 2 * jn], b2[4 * qq + 2 * jn + 1]);
    }
    __syncthreads();

    // ---------- token loop: 32 tokens (2 tiles) per warp-iteration ----------
    const int npairs = ntok >> 5;             // ntok multiple of 32
    const int wstep  = gridDim.x * 4;
    const int wp0    = blockIdx.x * 4 + wid;
    if (wp0 >= npairs) return;

    const long long e0 = (long long)g * H + 4 * q;          // row g
    const long long e1 = (long long)(g + 8) * H + 4 * q;    // row g+8

    auto loadpair = [&](int wp, float4& aA, float4& bA, float4& aB, float4& bB) {
        const float* p = x + ((long long)wp << 9);   // wp*32*H
        aA = *(const float4*)(p + e0);
        bA = *(const float4*)(p + e1);
        aB = *(const float4*)(p + 256 + e0);
        bB = *(const float4*)(p + 256 + e1);
    };

    // preamble: pairs i (v*) and i+1 (n*) loaded; A1 for pair i ready
    float4 vaA, vbA, vaB, vbB, naA, nbA, naB, nbB;
    loadpair(wp0, vaA, vbA, vaB, vbB);
    {
        int w1t = wp0 + wstep;
        if (w1t >= npairs) w1t = wp0;
        loadpair(w1t, naA, nbA, naB, nbB);
    }
    uint32_t A1A[4], A1B[4];
    ln_to_frag(vaA, vbA, A1A);
    ln_to_frag(vaB, vbB, A1B);

    for (int wp = wp0; wp < npairs; wp += wstep) {
        // ---- stage 2: prefetch pair i+2 (full iteration of slack) ----
        float4 paA, pbA, paB, pbB;
        {
            int nwp = wp + 2 * wstep;
            if (nwp >= npairs) nwp = wp;
            loadpair(nwp, paA, pbA, paB, pbB);
        }

        // ---- MMA1 tile A -> pack A2A (A1 ready from previous iteration) ----
        uint32_t A2A[4][4], A2B[4][4];
        {
            float C1[8][4];
            #pragma unroll
            for (int j = 0; j < 8; j++) {
                const float2 b = c1bs[j][q];
                mma_f16_bias(C1[j], A1A, B1[j], b.x, b.y);
            }
            #pragma unroll
            for (int s = 0; s < 4; s++) {
                A2A[s][0] = relu2(packh2(C1[2 * s][0],     C1[2 * s][1]));
                A2A[s][1] = relu2(packh2(C1[2 * s][2],     C1[2 * s][3]));
                A2A[s][2] = relu2(packh2(C1[2 * s + 1][0], C1[2 * s + 1][1]));
                A2A[s][3] = relu2(packh2(C1[2 * s + 1][2], C1[2 * s + 1][3]));
            }
        }
        // ---- MMA1 tile B -> pack A2B ----
        {
            float C1[8][4];
            #pragma unroll
            for (int j = 0; j < 8; j++) {
                const float2 b = c1bs[j][q];
                mma_f16_bias(C1[j], A1B, B1[j], b.x, b.y);
            }
            #pragma unroll
            for (int s = 0; s < 4; s++) {
                A2B[s][0] = relu2(packh2(C1[2 * s][0],     C1[2 * s][1]));
                A2B[s][1] = relu2(packh2(C1[2 * s][2],     C1[2 * s][3]));
                A2B[s][2] = relu2(packh2(C1[2 * s + 1][0], C1[2 * s + 1][1]));
                A2B[s][3] = relu2(packh2(C1[2 * s + 1][2], C1[2 * s + 1][3]));
            }
        }

        // ---- stage 1: LN-ahead for pair i+1 (x landed a full iter ago) ----
        uint32_t A1nA[4], A1nB[4];
        ln_to_frag(naA, nbA, A1nA);
        ln_to_frag(naB, nbB, A1nB);

        // ---- MMA2: four independent chains, bias-init on first k-step ----
        float C2A[2][4], C2B[2][4];
        {
            const float2 b0 = c2bs[0][q];
            const float2 b1v = c2bs[1][q];
            mma_f16_bias(C2A[0], A2A[0], B2[0][0], b0.x, b0.y);
            mma_f16_bias(C2B[0], A2B[0], B2[0][0], b0.x, b0.y);
            mma_f16_bias(C2A[1], A2A[0], B2[0][1], b1v.x, b1v.y);
            mma_f16_bias(C2B[1], A2B[0], B2[0][1], b1v.x, b1v.y);
        }
        #pragma unroll
        for (int s = 1; s < 4; s++) {
            mma_f16(C2A[0], A2A[s], B2[s][0]);
            mma_f16(C2B[0], A2B[s], B2[s][0]);
            mma_f16(C2A[1], A2A[s], B2[s][1]);
            mma_f16(C2B[1], A2B[s], B2[s][1]);
        }

        // ---- residual + coalesced STG.128 (both tiles) ----
        {
            float* p = out + ((long long)wp << 9);
            *(float4*)(p + e0)       = make_float4(C2A[0][0] + vaA.x, C2A[0][1] + vaA.y,
                                                   C2A[1][0] + vaA.z, C2A[1][1] + vaA.w);
            *(float4*)(p + e1)       = make_float4(C2A[0][2] + vbA.x, C2A[0][3] + vbA.y,
                                                   C2A[1][2] + vbA.z, C2A[1][3] + vbA.w);
            *(float4*)(p + 256 + e0) = make_float4(C2B[0][0] + vaB.x, C2B[0][1] + vaB.y,
                                                   C2B[1][0] + vaB.z, C2B[1][1] + vaB.w);
            *(float4*)(p + 256 + e1) = make_float4(C2B[0][2] + vbB.x, C2B[0][3] + vbB.y,
                                                   C2B[1][2] + vbB.z, C2B[1][3] + vbB.w);
        }

        // ---- rotate pipeline state ----
        vaA = naA; vbA = nbA; vaB = naB; vbB = nbB;
        naA = paA; nbA = pbA; naB = paB; nbB = pbB;
        A1A[0] = A1nA[0]; A1A[1] = A1nA[1]; A1A[2] = A1nA[2]; A1A[3] = A1nA[3];
        A1B[0] = A1nB[0]; A1B[1] = A1nB[1]; A1B[2] = A1nB[2]; A1B[3] = A1nB[3];
    }
}

extern "C" void kernel_launch(void* const* d_in, const int* in_sizes, int n_in,
                              void* d_out, int out_size) {
    const float* x     = (const float*)d_in[0];
    const float* gamma = (const float*)d_in[1];
    const float* beta  = (const float*)d_in[2];
    const float* w1    = (const float*)d_in[3];
    const float* b1    = (const float*)d_in[4];
    const float* w2    = (const float*)d_in[5];
    const float* b2    = (const float*)d_in[6];
    float* out         = (float*)d_out;

    const int ntok = in_sizes[0] / H;   // 1,048,576 (multiple of 32)
    const int threads = 128;            // 4 warps x 32 tokens
    int blocks = 148 * 3;               // persistent grid-stride, 3 CTAs/SM
    ffn_mma<<<blocks, threads>>>(x, gamma, beta, w1, b1, w2, b2, out, ntok);
}